// round 5
// baseline (speedup 1.0000x reference)
#include <cuda_runtime.h>

// NonMaximaSuppression2d: x (8,32,512,512) fp32.
// m = max over 8 neighbors (replicate pad), floored at 0 (zeroed center tap).
// out = x * (x > m).
// R3: horizontal halo via warp shuffles (LDG/row 3x -> ~1.06x), explicit
// 2-row prefetch pipeline, RPT back to 16.

#define HH 512
#define WW 512
#define RPT 16          // rows per thread strip
#define TPB 128         // threads per block = WW/4 float4 groups

struct RowRegs {
    float4 v;   // 4 center values
    float  l;   // value at col-1
    float  r;   // value at col+4
};

__device__ __forceinline__ void load_row(const float* __restrict__ img,
                                         int y, int c, int lane, RowRegs& rr) {
    int yc = min(max(y, 0), HH - 1);
    const float* p = img + (size_t)yc * WW + c;
    rr.v = *reinterpret_cast<const float4*>(p);
    // horizontal halo from neighbor lanes (warp covers 128 contiguous floats)
    rr.l = __shfl_up_sync(0xffffffffu, rr.v.w, 1);
    rr.r = __shfl_down_sync(0xffffffffu, rr.v.x, 1);
    if (lane == 0)  rr.l = (c > 0)      ? __ldg(p - 1) : rr.v.x;
    if (lane == 31) rr.r = (c + 4 < WW) ? __ldg(p + 4) : rr.v.w;
}

// max of 3 horizontally adjacent values per lane (rows above/below)
__device__ __forceinline__ float4 hmax3(const RowRegs& rr) {
    float4 h;
    h.x = fmaxf(fmaxf(rr.l,   rr.v.x), rr.v.y);
    h.y = fmaxf(fmaxf(rr.v.x, rr.v.y), rr.v.z);
    h.z = fmaxf(fmaxf(rr.v.y, rr.v.z), rr.v.w);
    h.w = fmaxf(fmaxf(rr.v.z, rr.v.w), rr.r);
    return h;
}

// max of the 2 horizontal neighbors (center excluded; for the center row)
__device__ __forceinline__ float4 hmax2(const RowRegs& rr) {
    float4 h;
    h.x = fmaxf(rr.l,   rr.v.y);
    h.y = fmaxf(rr.v.x, rr.v.z);
    h.z = fmaxf(rr.v.y, rr.v.w);
    h.w = fmaxf(rr.v.z, rr.r);
    return h;
}

__global__ __launch_bounds__(TPB)
void nms2d_kernel(const float* __restrict__ x, float* __restrict__ out) {
    const int tiles_per_img = HH / RPT;             // 32
    const int img  = blockIdx.x / tiles_per_img;
    const int tile = blockIdx.x % tiles_per_img;

    const float* in = x   + (size_t)img * HH * WW;
    float*       o  = out + (size_t)img * HH * WW;

    const int c    = threadIdx.x * 4;               // 0..508
    const int lane = threadIdx.x & 31;
    const int y0   = tile * RPT;

    // rolling window: r0=y-1, r1=y, r2=y+1, r3=prefetch y+2
    RowRegs r0, r1, r2, r3;
    load_row(in, y0 - 1, c, lane, r0);
    load_row(in, y0,     c, lane, r1);
    load_row(in, y0 + 1, c, lane, r2);

    float* op = o + (size_t)y0 * WW + c;

    #pragma unroll
    for (int i = 0; i < RPT; i++) {
        // prefetch 2 rows ahead (peeled on the last iteration: constant-folded)
        if (i < RPT - 1)
            load_row(in, y0 + i + 2, c, lane, r3);

        float4 mp = hmax3(r0);
        float4 mc = hmax2(r1);
        float4 mn = hmax3(r2);

        // fold the zeroed-center-tap floor (reference inits max at 0)
        float4 m;
        m.x = fmaxf(fmaxf(fmaxf(mp.x, mc.x), mn.x), 0.0f);
        m.y = fmaxf(fmaxf(fmaxf(mp.y, mc.y), mn.y), 0.0f);
        m.z = fmaxf(fmaxf(fmaxf(mp.z, mc.z), mn.z), 0.0f);
        m.w = fmaxf(fmaxf(fmaxf(mp.w, mc.w), mn.w), 0.0f);

        float4 xc = r1.v;
        float4 r;
        r.x = (xc.x > m.x) ? xc.x : 0.0f;
        r.y = (xc.y > m.y) ? xc.y : 0.0f;
        r.z = (xc.z > m.z) ? xc.z : 0.0f;
        r.w = (xc.w > m.w) ? xc.w : 0.0f;

        __stcs(reinterpret_cast<float4*>(op), r);
        op += WW;

        r0 = r1;
        r1 = r2;
        r2 = r3;
    }
}

extern "C" void kernel_launch(void* const* d_in, const int* in_sizes, int n_in,
                              void* d_out, int out_size) {
    const float* x = (const float*)d_in[0];
    float* out = (float*)d_out;

    const int n_img = in_sizes[0] / (HH * WW);      // B*C = 256
    const int blocks = n_img * (HH / RPT);          // 8192

    nms2d_kernel<<<blocks, TPB>>>(x, out);
}

// round 6
// speedup vs baseline: 1.1766x; 1.1766x over previous
#include <cuda_runtime.h>

// NonMaximaSuppression2d: x (8,32,512,512) fp32.
// m = max over 8 neighbors (replicate pad), floored at 0 (zeroed center tap).
// out = x * (x > m).
// R5: revert shuffles/prefetch (regs>32 killed occupancy; SHFL serialized the
// chain). R2 body + RPT=8: halo re-reads are L2 hits (DRAM already at traffic
// floor), 16384 CTAs -> ~7 waves -> better tail. regs must stay <=32.

#define HH 512
#define WW 512
#define RPT 8           // rows per thread strip
#define TPB 128         // threads per block = WW/4 float4 groups

struct RowRegs {
    float4 v;   // 4 center values
    float  l;   // value at col-1 (replicated at left edge)
    float  r;   // value at col+4 (replicated at right edge)
};

__device__ __forceinline__ void load_row(const float* __restrict__ img,
                                         int y, int c, RowRegs& rr) {
    int yc = min(max(y, 0), HH - 1);
    const float* p = img + (size_t)yc * WW + c;
    rr.v = *reinterpret_cast<const float4*>(p);
    // edge scalars hit the same 128B lines as neighbor lanes' vectors -> L1
    rr.l = (c > 0)      ? __ldg(p - 1) : rr.v.x;
    rr.r = (c + 4 < WW) ? __ldg(p + 4) : rr.v.w;
}

// max of 3 horizontally adjacent values per lane (rows above/below)
__device__ __forceinline__ float4 hmax3(const RowRegs& rr) {
    float4 h;
    h.x = fmaxf(fmaxf(rr.l,   rr.v.x), rr.v.y);
    h.y = fmaxf(fmaxf(rr.v.x, rr.v.y), rr.v.z);
    h.z = fmaxf(fmaxf(rr.v.y, rr.v.z), rr.v.w);
    h.w = fmaxf(fmaxf(rr.v.z, rr.v.w), rr.r);
    return h;
}

// max of the 2 horizontal neighbors (center excluded; for the center row)
__device__ __forceinline__ float4 hmax2(const RowRegs& rr) {
    float4 h;
    h.x = fmaxf(rr.l,   rr.v.y);
    h.y = fmaxf(rr.v.x, rr.v.z);
    h.z = fmaxf(rr.v.y, rr.v.w);
    h.w = fmaxf(rr.v.z, rr.r);
    return h;
}

__global__ __launch_bounds__(TPB)
void nms2d_kernel(const float* __restrict__ x, float* __restrict__ out) {
    const int tiles_per_img = HH / RPT;             // 64
    const int img  = blockIdx.x / tiles_per_img;
    const int tile = blockIdx.x % tiles_per_img;

    const float* in = x   + (size_t)img * HH * WW;
    float*       o  = out + (size_t)img * HH * WW;

    const int c  = threadIdx.x * 4;                 // 0..508
    const int y0 = tile * RPT;

    RowRegs prev, cur, next;
    load_row(in, y0 - 1, c, prev);
    load_row(in, y0,     c, cur);

    float* op = o + (size_t)y0 * WW + c;

    #pragma unroll
    for (int i = 0; i < RPT; i++) {
        load_row(in, y0 + i + 1, c, next);

        float4 mp = hmax3(prev);
        float4 mc = hmax2(cur);
        float4 mn = hmax3(next);

        // fold the zeroed-center-tap floor (reference inits max at 0)
        float4 m;
        m.x = fmaxf(fmaxf(fmaxf(mp.x, mc.x), mn.x), 0.0f);
        m.y = fmaxf(fmaxf(fmaxf(mp.y, mc.y), mn.y), 0.0f);
        m.z = fmaxf(fmaxf(fmaxf(mp.z, mc.z), mn.z), 0.0f);
        m.w = fmaxf(fmaxf(fmaxf(mp.w, mc.w), mn.w), 0.0f);

        float4 xc = cur.v;
        float4 r;
        r.x = (xc.x > m.x) ? xc.x : 0.0f;
        r.y = (xc.y > m.y) ? xc.y : 0.0f;
        r.z = (xc.z > m.z) ? xc.z : 0.0f;
        r.w = (xc.w > m.w) ? xc.w : 0.0f;

        // streaming store: output never re-read; keep L2 for input halos
        __stcs(reinterpret_cast<float4*>(op), r);
        op += WW;

        prev = cur;
        cur  = next;
    }
}

extern "C" void kernel_launch(void* const* d_in, const int* in_sizes, int n_in,
                              void* d_out, int out_size) {
    const float* x = (const float*)d_in[0];
    float* out = (float*)d_out;

    const int n_img = in_sizes[0] / (HH * WW);      // B*C = 256
    const int blocks = n_img * (HH / RPT);          // 16384

    nms2d_kernel<<<blocks, TPB>>>(x, out);
}

// round 7
// speedup vs baseline: 1.2058x; 1.0249x over previous
#include <cuda_runtime.h>

// NonMaximaSuppression2d: x (8,32,512,512) fp32.
// m = max over 8 neighbors (replicate pad), floored at 0 (zeroed center tap).
// out = x * (x > m).
// R6: RPT 8->4. Trend RPT {32,16,8} -> {86.0,87.2,79.4}us ncu shows more
// CTAs/smoother waves wins while L2 absorbs the halo. 32768 CTAs, ~14 waves.
// Body unchanged: 32 regs, 16 CTAs/SM, __stcs streaming stores.

#define HH 512
#define WW 512
#define RPT 4           // rows per thread strip
#define TPB 128         // threads per block = WW/4 float4 groups

struct RowRegs {
    float4 v;   // 4 center values
    float  l;   // value at col-1 (replicated at left edge)
    float  r;   // value at col+4 (replicated at right edge)
};

__device__ __forceinline__ void load_row(const float* __restrict__ img,
                                         int y, int c, RowRegs& rr) {
    int yc = min(max(y, 0), HH - 1);
    const float* p = img + (size_t)yc * WW + c;
    rr.v = *reinterpret_cast<const float4*>(p);
    // edge scalars hit the same 128B lines as neighbor lanes' vectors -> L1
    rr.l = (c > 0)      ? __ldg(p - 1) : rr.v.x;
    rr.r = (c + 4 < WW) ? __ldg(p + 4) : rr.v.w;
}

// max of 3 horizontally adjacent values per lane (rows above/below)
__device__ __forceinline__ float4 hmax3(const RowRegs& rr) {
    float4 h;
    h.x = fmaxf(fmaxf(rr.l,   rr.v.x), rr.v.y);
    h.y = fmaxf(fmaxf(rr.v.x, rr.v.y), rr.v.z);
    h.z = fmaxf(fmaxf(rr.v.y, rr.v.z), rr.v.w);
    h.w = fmaxf(fmaxf(rr.v.z, rr.v.w), rr.r);
    return h;
}

// max of the 2 horizontal neighbors (center excluded; for the center row)
__device__ __forceinline__ float4 hmax2(const RowRegs& rr) {
    float4 h;
    h.x = fmaxf(rr.l,   rr.v.y);
    h.y = fmaxf(rr.v.x, rr.v.z);
    h.z = fmaxf(rr.v.y, rr.v.w);
    h.w = fmaxf(rr.v.z, rr.r);
    return h;
}

__global__ __launch_bounds__(TPB)
void nms2d_kernel(const float* __restrict__ x, float* __restrict__ out) {
    const int tiles_per_img = HH / RPT;             // 128
    const int img  = blockIdx.x / tiles_per_img;
    const int tile = blockIdx.x % tiles_per_img;

    const float* in = x   + (size_t)img * HH * WW;
    float*       o  = out + (size_t)img * HH * WW;

    const int c  = threadIdx.x * 4;                 // 0..508
    const int y0 = tile * RPT;

    RowRegs prev, cur, next;
    load_row(in, y0 - 1, c, prev);
    load_row(in, y0,     c, cur);

    float* op = o + (size_t)y0 * WW + c;

    #pragma unroll
    for (int i = 0; i < RPT; i++) {
        load_row(in, y0 + i + 1, c, next);

        float4 mp = hmax3(prev);
        float4 mc = hmax2(cur);
        float4 mn = hmax3(next);

        // fold the zeroed-center-tap floor (reference inits max at 0)
        float4 m;
        m.x = fmaxf(fmaxf(fmaxf(mp.x, mc.x), mn.x), 0.0f);
        m.y = fmaxf(fmaxf(fmaxf(mp.y, mc.y), mn.y), 0.0f);
        m.z = fmaxf(fmaxf(fmaxf(mp.z, mc.z), mn.z), 0.0f);
        m.w = fmaxf(fmaxf(fmaxf(mp.w, mc.w), mn.w), 0.0f);

        float4 xc = cur.v;
        float4 r;
        r.x = (xc.x > m.x) ? xc.x : 0.0f;
        r.y = (xc.y > m.y) ? xc.y : 0.0f;
        r.z = (xc.z > m.z) ? xc.z : 0.0f;
        r.w = (xc.w > m.w) ? xc.w : 0.0f;

        // streaming store: output never re-read; keep L2 for input halos
        __stcs(reinterpret_cast<float4*>(op), r);
        op += WW;

        prev = cur;
        cur  = next;
    }
}

extern "C" void kernel_launch(void* const* d_in, const int* in_sizes, int n_in,
                              void* d_out, int out_size) {
    const float* x = (const float*)d_in[0];
    float* out = (float*)d_out;

    const int n_img = in_sizes[0] / (HH * WW);      // B*C = 256
    const int blocks = n_img * (HH / RPT);          // 32768

    nms2d_kernel<<<blocks, TPB>>>(x, out);
}